// round 14
// baseline (speedup 1.0000x reference)
#include <cuda_runtime.h>
#include <cuda_fp16.h>
#include <cstdint>

#define HW 192
#define F 100
#define CP 112            // padded channel count (stored)
#define PP 112            // conv_hidden smem pitch in halves (224B; XOR-swizzled -> conflict-free)
#define PITCH 120         // kp smem pitch (conflict-free)
#define KK 441
#define KKP 448
#define LGP 66            // logits smem pitch in halves (132B -> lane-conflict-free reads)

// Activation ping-pong buffers: fp16 NHWC[112]: 2*192*192*112 halves = 16.5 MB each.
// Pad channels 100..111 are never written by any kernel; they remain the
// zero-initialized value of __device__ globals (required by conv_hidden's K-MACs).
__device__ __half g_act0[2 * HW * HW * CP];
__device__ __half g_act1[2 * HW * HW * CP];
// Transformed hidden weights: [layer7][tap25][co128][ci112] fp16, 16B-chunk swizzled.
// Only (co<100, ci-image of ci<100) entries are ever written; the rest stay
// zero from static initialization (read as zero-pad by conv_hidden staging).
__device__ __half g_wt[7 * 25 * 128 * CP];
// Transformed kp weights: [448][112] fp16. Only co<441, ci<100 written; rest zero-init.
__device__ __half g_wkp[KKP * CP];

// ---------------------------------------------------------------------------
// PTX helpers
// ---------------------------------------------------------------------------
__device__ __forceinline__ uint32_t smem_u32(const void* p) {
    return (uint32_t)__cvta_generic_to_shared(p);
}
__device__ __forceinline__ void ldm_x4(uint32_t* r, uint32_t addr) {
    asm volatile("ldmatrix.sync.aligned.m8n8.x4.shared.b16 {%0,%1,%2,%3}, [%4];"
                 : "=r"(r[0]), "=r"(r[1]), "=r"(r[2]), "=r"(r[3]) : "r"(addr));
}
__device__ __forceinline__ void mma16816(float* c, const uint32_t* a, const uint32_t* b) {
    asm volatile(
        "mma.sync.aligned.m16n8k16.row.col.f32.f16.f16.f32 "
        "{%0,%1,%2,%3}, {%4,%5,%6,%7}, {%8,%9}, {%0,%1,%2,%3};"
        : "+f"(c[0]), "+f"(c[1]), "+f"(c[2]), "+f"(c[3])
        : "r"(a[0]), "r"(a[1]), "r"(a[2]), "r"(a[3]), "r"(b[0]), "r"(b[1]));
}
__device__ __forceinline__ void cp16(uint32_t dst, const void* src) {
    asm volatile("cp.async.cg.shared.global [%0], [%1], 16;" :: "r"(dst), "l"(src));
}
__device__ __forceinline__ void cp16z(uint32_t dst, const void* src, int srcsz) {
    asm volatile("cp.async.cg.shared.global [%0], [%1], 16, %2;"
                 :: "r"(dst), "l"(src), "r"(srcsz));
}
__device__ __forceinline__ void cp_commit() { asm volatile("cp.async.commit_group;"); }
template <int N>
__device__ __forceinline__ void cp_wait() {
    asm volatile("cp.async.wait_group %0;" :: "n"(N));
}

// ---------------------------------------------------------------------------
// Weight transforms.
// wt_transform: one block per (layer, co<100). Coalesced 2500-float read of
// w_hid[l][co][:][:], smem transpose (stride 25 is coprime with 32 banks ->
// conflict-free), write only nonzero entries of g_wt[l][tap][co][ci^swz].
// Produces bit-identical g_wt contents to the old output-indexed version.
// ---------------------------------------------------------------------------
__global__ void wt_transform(const float* __restrict__ w_hid) {
    __shared__ float sw[F * 25];
    const int l = blockIdx.x / F;
    const int co = blockIdx.x % F;
    const int t = threadIdx.x;

    const float* src = w_hid + ((size_t)l * F + co) * (F * 25);
    for (int i = t; i < F * 25; i += 128) sw[i] = src[i];
    __syncthreads();

    const int x = ((co >> 2) & 1) ? 8 : 0;     // 16B-chunk swizzle (self-inverse)
    for (int i = t; i < 25 * F; i += 128) {
        int tap = i / F, ci = i - tap * F;
        int ci_out = ci ^ x;                    // < 112 for all ci < 100
        g_wt[(((size_t)l * 25 + tap) * 128 + co) * CP + ci_out] =
            __float2half(sw[ci * 25 + tap]);
    }
}

__global__ void wkp_transform(const float* __restrict__ w_kp) {
    int idx = blockIdx.x * 256 + threadIdx.x;
    if (idx >= KK * F) return;
    int co = idx / F, ci = idx - co * F;
    g_wkp[(size_t)co * CP + ci] = __float2half(w_kp[idx]);
}

// ---------------------------------------------------------------------------
// Input conv 5x5 (3->100) + relu, fp32 FFMA, output fp16 NHWC[112].
// ---------------------------------------------------------------------------
__global__ __launch_bounds__(256)
void conv_in(const float* __restrict__ in, const float* __restrict__ w,
             const float* __restrict__ bias, __half* __restrict__ out) {
    __shared__ float s_in[3][36][37];
    __shared__ float s_w[3][25][10];

    const int t = threadIdx.x;
    const int tx = t & 15, ty = t >> 4;
    const int tileX = (blockIdx.x % 6) * 32;
    const int tileY = (blockIdx.x / 6) * 32;
    const int co0 = blockIdx.y * 10;
    const int b = blockIdx.z;
    const float* inb = in + (size_t)b * 3 * (HW * HW);

    for (int i = t; i < 3 * 36 * 36; i += 256) {
        int cc = i / (36 * 36);
        int rem = i - cc * (36 * 36);
        int r = rem / 36, c = rem - r * 36;
        int gy = tileY + r - 2, gx = tileX + c - 2;
        float v = 0.f;
        if ((unsigned)gy < HW && (unsigned)gx < HW)
            v = inb[(size_t)cc * (HW * HW) + gy * HW + gx];
        s_in[cc][r][c] = v;
    }
    for (int i = t; i < 3 * 250; i += 256) {
        int co = i % 10;
        int tap = (i / 10) % 25;
        int cc = i / 250;
        s_w[cc][tap][co] = w[((size_t)(co0 + co) * 3 + cc) * 25 + tap];
    }
    __syncthreads();

    float acc[10][4];
#pragma unroll
    for (int c = 0; c < 10; c++)
#pragma unroll
        for (int p = 0; p < 4; p++) acc[c][p] = 0.f;

#pragma unroll
    for (int cc = 0; cc < 3; cc++) {
#pragma unroll 1
        for (int ky = 0; ky < 5; ky++) {
            const int r0 = 2 * ty + ky;
#pragma unroll
            for (int kx = 0; kx < 5; kx++) {
                const int c0 = 2 * tx + kx;
                float x00 = s_in[cc][r0][c0];
                float x01 = s_in[cc][r0][c0 + 1];
                float x10 = s_in[cc][r0 + 1][c0];
                float x11 = s_in[cc][r0 + 1][c0 + 1];
                const int tap = ky * 5 + kx;
#pragma unroll
                for (int co = 0; co < 10; co++) {
                    float wv = s_w[cc][tap][co];
                    acc[co][0] = fmaf(wv, x00, acc[co][0]);
                    acc[co][1] = fmaf(wv, x01, acc[co][1]);
                    acc[co][2] = fmaf(wv, x10, acc[co][2]);
                    acc[co][3] = fmaf(wv, x11, acc[co][3]);
                }
            }
        }
    }

#pragma unroll
    for (int co = 0; co < 10; co++) {
        float bb = bias[co0 + co];
#pragma unroll
        for (int p = 0; p < 4; p++) {
            int ly = 2 * ty + (p >> 1);
            int lx = 2 * tx + (p & 1);
            float v = acc[co][p] + bb;
            v = v > 0.f ? v : 0.f;
            out[((size_t)(b * HW + tileY + ly) * HW + tileX + lx) * CP + co0 + co] =
                __float2half(v);
        }
    }
}

// ---------------------------------------------------------------------------
// Hidden conv 5x5 (100->100) + relu, fp16 tensor cores. (Round-12, unchanged.)
// CTA: 256 thr = 8 warps as 2M x 4N. Tile: 112 couts x 128 pixels (16w x 8h).
// ---------------------------------------------------------------------------
__global__ __launch_bounds__(256, 2)
void conv_hidden(const __half* __restrict__ act_in, const __half* __restrict__ wt,
                 const float* __restrict__ bias, __half* __restrict__ act_out) {
    extern __shared__ __align__(128) __half smem[];
    __half* s_patch = smem;                     // 240 pixel slots * PP halves = 53760 B
    __half* s_A = smem + 240 * PP;              // 2 buffers * 112 * PP = 50176 B
    const uint32_t A_BYTES = 112 * PP * 2;      // 25088

    const int t = threadIdx.x;
    const int lane = t & 31, w = t >> 5;
    const int nw = w & 3, mw = w >> 2;          // 4 N x 2 M
    const int g = lane >> 2, tg = lane & 3;
    const int tileX = (blockIdx.x % 12) * 16;
    const int tileY = (blockIdx.x / 12) * 8;
    const int b = blockIdx.z;
    const int co0 = mw * 64;
    const int nmi = mw ? 3 : 4;

    const uint32_t sp = smem_u32(s_patch);
    const uint32_t sA0 = smem_u32(s_A);

    {
        const __half* actb = act_in + (size_t)b * HW * HW * CP;
        for (int i = t; i < 240 * 14; i += 256) {
            int pix = i / 14, j = i % 14;
            int r = pix / 20, c = pix % 20;
            int gy = tileY + r - 2, gx = tileX + c - 2;
            bool ok = (unsigned)gy < HW && (unsigned)gx < HW;
            const char* src = ok
                ? (const char*)&actb[((size_t)gy * HW + gx) * CP] + j * 16
                : (const char*)actb;
            uint32_t dst = sp + (uint32_t)pix * (PP * 2) +
                           ((uint32_t)(j * 16) ^ (((pix >> 2) & 1) << 4));
            cp16z(dst, src, ok ? 16 : 0);
        }
    }
    {
        const char* wsrc = (const char*)wt;
        for (int i = t; i < 1568; i += 256)
            cp16(sA0 + (uint32_t)i * 16, wsrc + (size_t)i * 16);
    }
    cp_commit();

    uint32_t a_base[4];
#pragma unroll
    for (int mi = 0; mi < 4; mi++) {
        int row = co0 + mi * 16 + (lane & 15);
        if (row > 111) row = 111;
        uint32_t acol2 = (uint32_t)(lane >> 4) * 16;
        a_base[mi] = sA0 + (uint32_t)row * (PP * 2) +
                     (acol2 ^ (((uint32_t)(row >> 2) & 1) << 4));
    }

    uint32_t b_base[2];
    uint32_t s0pack = 0;
    {
        int sub = lane >> 3, pix = lane & 7;
#pragma unroll
        for (int j = 0; j < 2; j++) {
            int ni = 2 * j + (sub >> 1);
            int khalf = sub & 1;
            int pr0 = nw * 2 + (ni >> 1);
            int pc0 = (ni & 1) * 8 + pix;
            int s0 = pr0 * 20 + pc0;
            b_base[j] = sp + (uint32_t)s0 * (PP * 2) + (uint32_t)khalf * 16;
            s0pack |= (uint32_t)s0 << (8 * j);
        }
    }

    float acc[4][4][4];
#pragma unroll
    for (int mi = 0; mi < 4; mi++)
#pragma unroll
        for (int ni = 0; ni < 4; ni++)
#pragma unroll
            for (int p = 0; p < 4; p++) acc[mi][ni][p] = 0.f;

    cp_wait<0>();
    __syncthreads();

#pragma unroll 1
    for (int tap = 0; tap < 25; tap++) {
        if (tap < 24) {
            const char* wsrc = (const char*)(wt + (size_t)(tap + 1) * 128 * CP);
            uint32_t dst = sA0 + ((tap + 1) & 1) * A_BYTES;
            for (int i = t; i < 1568; i += 256)
                cp16(dst + (uint32_t)i * 16, wsrc + (size_t)i * 16);
            cp_commit();
        }

        const uint32_t aoff = (tap & 1) * A_BYTES;
        const int ky = tap / 5, kx = tap % 5;
        const int ds = ky * 20 + kx;
        const uint32_t dsb = (uint32_t)ds * (PP * 2);

        uint32_t b_tap[2];
#pragma unroll
        for (int j = 0; j < 2; j++) {
            uint32_t s0j = (s0pack >> (8 * j)) & 255u;
            uint32_t swz = ((s0j + (uint32_t)ds) << 2) & 16u;
            b_tap[j] = (b_base[j] + dsb) ^ swz;
        }

        if (mw == 0) {
#pragma unroll
            for (int kc = 0; kc < CP; kc += 16) {
                uint32_t a[4][4];
#pragma unroll
                for (int mi = 0; mi < 4; mi++) ldm_x4(a[mi], a_base[mi] + aoff + kc * 2);
                uint32_t bf[4][2];
#pragma unroll
                for (int j = 0; j < 2; j++) {
                    uint32_t r[4];
                    ldm_x4(r, b_tap[j] + kc * 2);
                    bf[2 * j][0] = r[0]; bf[2 * j][1] = r[1];
                    bf[2 * j + 1][0] = r[2]; bf[2 * j + 1][1] = r[3];
                }
#pragma unroll
                for (int mi = 0; mi < 4; mi++)
#pragma unroll
                    for (int ni = 0; ni < 4; ni++)
                        mma16816(acc[mi][ni], a[mi], bf[ni]);
            }
        } else {
#pragma unroll
            for (int kc = 0; kc < CP; kc += 16) {
                uint32_t a[3][4];
#pragma unroll
                for (int mi = 0; mi < 3; mi++) ldm_x4(a[mi], a_base[mi] + aoff + kc * 2);
                uint32_t bf[4][2];
#pragma unroll
                for (int j = 0; j < 2; j++) {
                    uint32_t r[4];
                    ldm_x4(r, b_tap[j] + kc * 2);
                    bf[2 * j][0] = r[0]; bf[2 * j][1] = r[1];
                    bf[2 * j + 1][0] = r[2]; bf[2 * j + 1][1] = r[3];
                }
#pragma unroll
                for (int mi = 0; mi < 3; mi++)
#pragma unroll
                    for (int ni = 0; ni < 4; ni++)
                        mma16816(acc[mi][ni], a[mi], bf[ni]);
            }
        }

        if (tap < 24) {
            cp_wait<0>();
            __syncthreads();
        }
    }

#pragma unroll
    for (int mi = 0; mi < 4; mi++) {
        if (mi >= nmi) break;
        int co_a = co0 + mi * 16 + g;
        int co_b = co_a + 8;
        float ba = (co_a < F) ? bias[co_a] : 0.f;
        float bb = (co_b < F) ? bias[co_b] : 0.f;
#pragma unroll
        for (int ni = 0; ni < 4; ni++) {
            int py = tileY + nw * 2 + (ni >> 1);
            int px = tileX + ((ni & 1) << 3) + 2 * tg;
            size_t base = ((size_t)(b * HW + py) * HW + px) * CP;
            if (co_a < F) {
                float v0 = acc[mi][ni][0] + ba; v0 = v0 > 0.f ? v0 : 0.f;
                float v1 = acc[mi][ni][1] + ba; v1 = v1 > 0.f ? v1 : 0.f;
                act_out[base + co_a] = __float2half(v0);
                act_out[base + CP + co_a] = __float2half(v1);
            }
            if (co_b < F) {
                float v2 = acc[mi][ni][2] + bb; v2 = v2 > 0.f ? v2 : 0.f;
                float v3 = acc[mi][ni][3] + bb; v3 = v3 > 0.f ? v3 : 0.f;
                act_out[base + co_b] = __float2half(v2);
                act_out[base + CP + co_b] = __float2half(v3);
            }
        }
    }
}

// ---------------------------------------------------------------------------
// Fused kp: per CTA, 64 pixels (16x4 tile). GEMM over 4 chunks of 128 wkp
// rows -> logits in smem transposed [co][pix], then softmax + apply.
// s_patch aliases the s_A region (dead after GEMM) -> 2 CTAs/SM.
// ---------------------------------------------------------------------------
#define SMEM_KP2 (15360 + 30720 + 59136)   // s_px + s_A(/patch) + s_lg

__global__ __launch_bounds__(256, 2)
void kp_fused2(const __half* __restrict__ feat, const float* __restrict__ noisy,
               const __half* __restrict__ wkp, const float* __restrict__ b_kp,
               float* __restrict__ out) {
    extern __shared__ __align__(128) char smc[];
    __half* s_px = (__half*)smc;                            // [64][120]
    __half* s_A = (__half*)(smc + 15360);                   // [128][120]
    __half* s_lg = (__half*)(smc + 15360 + 30720);          // [448][66]
    float* s_patch = (float*)(smc + 15360);                 // [3][24][36], aliases s_A

    const int t = threadIdx.x;
    const int lane = t & 31, w = t >> 5;
    const int mw = w & 3, nw = w >> 2;
    const int g = lane >> 2, tg = lane & 3;
    const int tileX = (blockIdx.x % 12) * 16;
    const int tileY = (blockIdx.x / 12) * 4;
    const int b = blockIdx.z;

    {
        const __half* fb = feat + (size_t)b * HW * HW * CP;
        for (int i = t; i < 64 * 14; i += 256) {
            int pix = i / 14, j = i % 14;
            int gy = tileY + (pix >> 4), gx = tileX + (pix & 15);
            ((uint4*)&s_px[pix * PITCH])[j] =
                ((const uint4*)&fb[((size_t)gy * HW + gx) * CP])[j];
        }
    }

    uint32_t a_base[2];
#pragma unroll
    for (int mi = 0; mi < 2; mi++)
        a_base[mi] = smem_u32(&s_A[(mw * 32 + mi * 16 + (lane & 15)) * PITCH +
                                   (lane >> 4) * 8]);
    uint32_t b_base[2];
    {
        int sub = lane >> 3, pix8 = lane & 7;
#pragma unroll
        for (int j = 0; j < 2; j++) {
            int ni = 2 * j + (sub >> 1);
            int khalf = sub & 1;
            int pidx = nw * 32 + ni * 8 + pix8;
            b_base[j] = smem_u32(&s_px[pidx * PITCH + khalf * 8]);
        }
    }

#pragma unroll 1
    for (int cg = 0; cg < 4; cg++) {
        __syncthreads();   // staging done (cg=0) / prior chunk's s_A reads done
        for (int i = t; i < 128 * 14; i += 256) {
            int co = i / 14, j = i % 14;
            int row = cg * 128 + co;
            uint4 v = make_uint4(0, 0, 0, 0);
            if (row < KKP)
                v = ((const uint4*)&wkp[(size_t)row * CP])[j];
            ((uint4*)&s_A[co * PITCH])[j] = v;
        }
        __syncthreads();

        float acc[2][4][4];
#pragma unroll
        for (int mi = 0; mi < 2; mi++)
#pragma unroll
            for (int ni = 0; ni < 4; ni++)
#pragma unroll
                for (int p = 0; p < 4; p++) acc[mi][ni][p] = 0.f;

#pragma unroll
        for (int kc = 0; kc < CP; kc += 16) {
            uint32_t a[2][4];
#pragma unroll
            for (int mi = 0; mi < 2; mi++) ldm_x4(a[mi], a_base[mi] + kc * 2);
            uint32_t bf[4][2];
#pragma unroll
            for (int j = 0; j < 2; j++) {
                uint32_t r[4];
                ldm_x4(r, b_base[j] + kc * 2);
                bf[2 * j][0] = r[0]; bf[2 * j][1] = r[1];
                bf[2 * j + 1][0] = r[2]; bf[2 * j + 1][1] = r[3];
            }
#pragma unroll
            for (int mi = 0; mi < 2; mi++)
#pragma unroll
                for (int ni = 0; ni < 4; ni++)
                    mma16816(acc[mi][ni], a[mi], bf[ni]);
        }

#pragma unroll
        for (int mi = 0; mi < 2; mi++) {
            int co_a = cg * 128 + mw * 32 + mi * 16 + g;
            int co_b = co_a + 8;
            float ba = (co_a < KK) ? b_kp[co_a] : 0.f;
            float bb = (co_b < KK) ? b_kp[co_b] : 0.f;
#pragma unroll
            for (int ni = 0; ni < 4; ni++) {
                int pidx = nw * 32 + ni * 8 + 2 * tg;
                if (co_a < KK) {
                    __half2 h = __floats2half2_rn(acc[mi][ni][0] + ba,
                                                  acc[mi][ni][1] + ba);
                    *(__half2*)&s_lg[co_a * LGP + pidx] = h;
                }
                if (co_b < KK) {
                    __half2 h = __floats2half2_rn(acc[mi][ni][2] + bb,
                                                  acc[mi][ni][3] + bb);
                    *(__half2*)&s_lg[co_b * LGP + pidx] = h;
                }
            }
        }
    }
    __syncthreads();   // all s_A reads done; region reused for patch below

    // Stage noisy patch (fp32) into the dead s_A region.
    for (int i = t; i < 3 * 24 * 36; i += 256) {
        int c = i / (24 * 36);
        int rem = i - c * (24 * 36);
        int dy = rem / 36, dx = rem - dy * 36;
        int gy = tileY + dy - 10, gx = tileX + dx - 10;
        float v = 0.f;
        if ((unsigned)gy < HW && (unsigned)gx < HW)
            v = noisy[(((size_t)b * 3 + c) * HW + gy) * HW + gx];
        s_patch[(c * 24 + dy) * 36 + dx] = v;
    }
    __syncthreads();

#pragma unroll 1
    for (int it = 0; it < 8; it++) {
        int pidx = it * 8 + w;
        int py = pidx >> 4, pxl = pidx & 15;

        float L[14];
#pragma unroll
        for (int i = 0; i < 14; i++) {
            int j = i * 32 + lane;
            L[i] = (j < KK) ? __half2float(s_lg[j * LGP + pidx]) : -1e30f;
        }
        float m = -1e30f;
#pragma unroll
        for (int i = 0; i < 14; i++) m = fmaxf(m, L[i]);
#pragma unroll
        for (int o = 16; o; o >>= 1) m = fmaxf(m, __shfl_xor_sync(0xffffffffu, m, o));

        float se = 0.f, o0 = 0.f, o1 = 0.f, o2 = 0.f;
#pragma unroll
        for (int i = 0; i < 14; i++) {
            int j = i * 32 + lane;
            if (j < KK) {
                float e = __expf(L[i] - m);
                int ky = j / 21, kx = j - ky * 21;
                se += e;
                o0 += e * s_patch[(0 * 24 + py + ky) * 36 + pxl + kx];
                o1 += e * s_patch[(1 * 24 + py + ky) * 36 + pxl + kx];
                o2 += e * s_patch[(2 * 24 + py + ky) * 36 + pxl + kx];
            }
        }
#pragma unroll
        for (int o = 16; o; o >>= 1) {
            se += __shfl_xor_sync(0xffffffffu, se, o);
            o0 += __shfl_xor_sync(0xffffffffu, o0, o);
            o1 += __shfl_xor_sync(0xffffffffu, o1, o);
            o2 += __shfl_xor_sync(0xffffffffu, o2, o);
        }
        if (lane == 0) {
            float inv = 1.f / se;
            int y = tileY + py, x = tileX + pxl;
            out[(((size_t)b * 3 + 0) * HW + y) * HW + x] = o0 * inv;
            out[(((size_t)b * 3 + 1) * HW + y) * HW + x] = o1 * inv;
            out[(((size_t)b * 3 + 2) * HW + y) * HW + x] = o2 * inv;
        }
    }
}

// ---------------------------------------------------------------------------
extern "C" void kernel_launch(void* const* d_in, const int* in_sizes, int n_in,
                              void* d_out, int out_size) {
    const float* noisy = (const float*)d_in[0];
    const float* w_in  = (const float*)d_in[1];
    const float* b_in  = (const float*)d_in[2];
    const float* w_hid = (const float*)d_in[3];
    const float* b_hid = (const float*)d_in[4];
    const float* w_kp  = (const float*)d_in[5];
    const float* b_kp  = (const float*)d_in[6];
    float* out = (float*)d_out;

    __half *act0, *act1, *wt, *wkp;
    cudaGetSymbolAddress((void**)&act0, g_act0);
    cudaGetSymbolAddress((void**)&act1, g_act1);
    cudaGetSymbolAddress((void**)&wt, g_wt);
    cudaGetSymbolAddress((void**)&wkp, g_wkp);

    const int smem_hidden = 240 * PP * 2 + 2 * 112 * PP * 2;  // 103936 B
    cudaFuncSetAttribute(conv_hidden, cudaFuncAttributeMaxDynamicSharedMemorySize,
                         smem_hidden);
    cudaFuncSetAttribute(kp_fused2, cudaFuncAttributeMaxDynamicSharedMemorySize,
                         SMEM_KP2);

    wt_transform<<<7 * F, 128>>>(w_hid);
    wkp_transform<<<(KK * F + 255) / 256, 256>>>(w_kp);

    conv_in<<<dim3(36, 10, 2), 256>>>(noisy, w_in, b_in, act0);

    const __half* src = act0;
    __half* dst = act1;
    for (int l = 0; l < 7; l++) {
        conv_hidden<<<dim3(288, 1, 2), 256, smem_hidden>>>(
            src, wt + (size_t)l * 25 * 128 * CP, b_hid + l * F, dst);
        __half* tmp = (__half*)src;
        src = dst;
        dst = tmp;
    }

    kp_fused2<<<dim3(576, 1, 2), 256, SMEM_KP2>>>(src, noisy, wkp, b_kp, out);
}

// round 16
// speedup vs baseline: 1.0899x; 1.0899x over previous
#include <cuda_runtime.h>
#include <cuda_fp16.h>
#include <cstdint>

#define HW 192
#define F 100
#define CP 112            // padded channel count (stored)
#define PP 112            // conv_hidden smem pitch in halves (224B; XOR-swizzled -> conflict-free)
#define PITCH 120         // kp smem pitch (conflict-free)
#define PIN 40            // conv_in smem pitch in halves (80B -> conflict-free, no swizzle)
#define KK 441
#define KKP 448
#define LGP 66            // logits smem pitch in halves (132B -> lane-conflict-free reads)

// Activation ping-pong buffers: fp16 NHWC[112]. Pad channels 100..111 are never
// written; they stay zero from static initialization.
__device__ __half g_act0[2 * HW * HW * CP];
__device__ __half g_act1[2 * HW * HW * CP];
// Transformed hidden weights: [layer7][tap25][co128][ci112] fp16, 16B-chunk swizzled.
__device__ __half g_wt[7 * 25 * 128 * CP];
// Transformed kp weights: [448][112] fp16. Only co<441, ci<100 written; rest zero-init.
__device__ __half g_wkp[KKP * CP];
// Transformed input-conv weights: [ky5][co112][PIN] fp16, k = kx*3+ch (15 used + pad).
__device__ __half g_win[5 * CP * PIN];

// ---------------------------------------------------------------------------
// PTX helpers
// ---------------------------------------------------------------------------
__device__ __forceinline__ uint32_t smem_u32(const void* p) {
    return (uint32_t)__cvta_generic_to_shared(p);
}
__device__ __forceinline__ void ldm_x4(uint32_t* r, uint32_t addr) {
    asm volatile("ldmatrix.sync.aligned.m8n8.x4.shared.b16 {%0,%1,%2,%3}, [%4];"
                 : "=r"(r[0]), "=r"(r[1]), "=r"(r[2]), "=r"(r[3]) : "r"(addr));
}
__device__ __forceinline__ void mma16816(float* c, const uint32_t* a, const uint32_t* b) {
    asm volatile(
        "mma.sync.aligned.m16n8k16.row.col.f32.f16.f16.f32 "
        "{%0,%1,%2,%3}, {%4,%5,%6,%7}, {%8,%9}, {%0,%1,%2,%3};"
        : "+f"(c[0]), "+f"(c[1]), "+f"(c[2]), "+f"(c[3])
        : "r"(a[0]), "r"(a[1]), "r"(a[2]), "r"(a[3]), "r"(b[0]), "r"(b[1]));
}
__device__ __forceinline__ void cp16(uint32_t dst, const void* src) {
    asm volatile("cp.async.cg.shared.global [%0], [%1], 16;" :: "r"(dst), "l"(src));
}
__device__ __forceinline__ void cp16z(uint32_t dst, const void* src, int srcsz) {
    asm volatile("cp.async.cg.shared.global [%0], [%1], 16, %2;"
                 :: "r"(dst), "l"(src), "r"(srcsz));
}
__device__ __forceinline__ void cp_commit() { asm volatile("cp.async.commit_group;"); }
template <int N>
__device__ __forceinline__ void cp_wait() {
    asm volatile("cp.async.wait_group %0;" :: "n"(N));
}

// ---------------------------------------------------------------------------
// Weight transforms.
// ---------------------------------------------------------------------------
__global__ void wt_transform(const float* __restrict__ w_hid) {
    __shared__ float sw[F * 25];
    const int l = blockIdx.x / F;
    const int co = blockIdx.x % F;
    const int t = threadIdx.x;

    const float* src = w_hid + ((size_t)l * F + co) * (F * 25);
    for (int i = t; i < F * 25; i += 128) sw[i] = src[i];
    __syncthreads();

    const int x = ((co >> 2) & 1) ? 8 : 0;
    for (int i = t; i < 25 * F; i += 128) {
        int tap = i / F, ci = i - tap * F;
        int ci_out = ci ^ x;
        g_wt[(((size_t)l * 25 + tap) * 128 + co) * CP + ci_out] =
            __float2half(sw[ci * 25 + tap]);
    }
}

__global__ void wkp_transform(const float* __restrict__ w_kp) {
    int idx = blockIdx.x * 256 + threadIdx.x;
    if (idx >= KK * F) return;
    int co = idx / F, ci = idx - co * F;
    g_wkp[(size_t)co * CP + ci] = __float2half(w_kp[idx]);
}

// g_win[ky][co][k] with k = kx*3+ch (k<15), zero elsewhere. w_in: [100][3][5][5].
__global__ void win_transform(const float* __restrict__ w_in) {
    int idx = blockIdx.x * 256 + threadIdx.x;
    if (idx >= 5 * CP * PIN) return;
    int k = idx % PIN;
    int co = (idx / PIN) % CP;
    int ky = idx / (PIN * CP);
    float v = 0.f;
    if (k < 15 && co < F) {
        int kx = k / 3, ch = k % 3;
        v = w_in[(((size_t)co * 3 + ch) * 5 + ky) * 5 + kx];
    }
    g_win[idx] = __float2half(v);
}

// ---------------------------------------------------------------------------
// Input conv 5x5 (3->100) + relu via tensor cores.
// CTA: 256 thr = 8 warps (2M x 4N), tile 112 co x 128 px (16w x 8h).
// 5 ky-taps, each one m16n8k16 K-step with K = kx*3+ch (15 + 1 pad).
// B im2col tile: 192 slots (12 rows x 16 px) x 16 halves, pitch PIN=40.
// ---------------------------------------------------------------------------
// smem: s_B 192*40*2=15360 @0; s_A 5*112*40*2=44800 @15360; s_raw 720*4=2880 @60160.
#define SMEM_CIN 63040

__global__ __launch_bounds__(256, 2)
void conv_in_tc(const float* __restrict__ in, const __half* __restrict__ win,
                const float* __restrict__ bias, __half* __restrict__ out) {
    extern __shared__ __align__(128) char smc[];
    __half* s_B = (__half*)smc;                  // [192][PIN]
    __half* s_A = (__half*)(smc + 15360);        // [5][112][PIN]
    float* s_raw = (float*)(smc + 60160);        // [3][12][20]

    const int t = threadIdx.x;
    const int lane = t & 31, w = t >> 5;
    const int nw = w & 3, mw = w >> 2;
    const int g = lane >> 2, tg = lane & 3;
    const int tileX = (blockIdx.x % 12) * 16;
    const int tileY = (blockIdx.x / 12) * 8;
    const int b = blockIdx.z;
    const int co0 = mw * 64;
    const int nmi = mw ? 3 : 4;

    // Stage A (linear copy of pre-arranged g_win: 44800 B = 2800 chunks).
    {
        const uint32_t sA = smem_u32(s_A);
        for (int i = t; i < 2800; i += 256)
            cp16(sA + (uint32_t)i * 16, (const char*)win + (size_t)i * 16);
        cp_commit();
    }
    // Stage raw input 3 x 12 x 20 fp32 (zero at borders).
    {
        const float* inb = in + (size_t)b * 3 * (HW * HW);
        for (int i = t; i < 720; i += 256) {
            int ch = i / 240;
            int rem = i - ch * 240;
            int r = rem / 20, c = rem - r * 20;
            int gy = tileY + r - 2, gx = tileX + c - 2;
            float v = 0.f;
            if ((unsigned)gy < HW && (unsigned)gx < HW)
                v = inb[(size_t)ch * (HW * HW) + gy * HW + gx];
            s_raw[i] = v;
        }
    }
    __syncthreads();

    // Build im2col B tile: slot (r, c) -> vec[kx*3+ch] = raw[ch][r][c+kx].
    for (int i = t; i < 192 * 16; i += 256) {
        int slot = i >> 4, k = i & 15;
        int r = slot >> 4, c = slot & 15;
        __half v = __float2half(0.f);
        if (k < 15) {
            int kx = k / 3, ch = k - kx * 3;
            v = __float2half(s_raw[(ch * 12 + r) * 20 + c + kx]);
        }
        s_B[slot * PIN + k] = v;
    }
    cp_wait<0>();
    __syncthreads();

    uint32_t a_base[4];
#pragma unroll
    for (int mi = 0; mi < 4; mi++) {
        int row = co0 + mi * 16 + (lane & 15);
        if (row > 111) row = 111;
        a_base[mi] = smem_u32(&s_A[row * PIN + (lane >> 4) * 8]);
    }
    uint32_t b_base[2];
    {
        int sub = lane >> 3, pix = lane & 7;
#pragma unroll
        for (int j = 0; j < 2; j++) {
            int ni = 2 * j + (sub >> 1);
            int khalf = sub & 1;
            int pr0 = nw * 2 + (ni >> 1);
            int pc0 = (ni & 1) * 8 + pix;
            b_base[j] = smem_u32(&s_B[(pr0 * 16 + pc0) * PIN + khalf * 8]);
        }
    }

    float acc[4][4][4];
#pragma unroll
    for (int mi = 0; mi < 4; mi++)
#pragma unroll
        for (int ni = 0; ni < 4; ni++)
#pragma unroll
            for (int p = 0; p < 4; p++) acc[mi][ni][p] = 0.f;

#pragma unroll
    for (int ky = 0; ky < 5; ky++) {
        const uint32_t aoff = (uint32_t)ky * (CP * PIN * 2);
        const uint32_t boff = (uint32_t)ky * (16 * PIN * 2);
        uint32_t bf[4][2];
#pragma unroll
        for (int j = 0; j < 2; j++) {
            uint32_t r[4];
            ldm_x4(r, b_base[j] + boff);
            bf[2 * j][0] = r[0]; bf[2 * j][1] = r[1];
            bf[2 * j + 1][0] = r[2]; bf[2 * j + 1][1] = r[3];
        }
        if (mw == 0) {
            uint32_t a[4][4];
#pragma unroll
            for (int mi = 0; mi < 4; mi++) ldm_x4(a[mi], a_base[mi] + aoff);
#pragma unroll
            for (int mi = 0; mi < 4; mi++)
#pragma unroll
                for (int ni = 0; ni < 4; ni++)
                    mma16816(acc[mi][ni], a[mi], bf[ni]);
        } else {
            uint32_t a[3][4];
#pragma unroll
            for (int mi = 0; mi < 3; mi++) ldm_x4(a[mi], a_base[mi] + aoff);
#pragma unroll
            for (int mi = 0; mi < 3; mi++)
#pragma unroll
                for (int ni = 0; ni < 4; ni++)
                    mma16816(acc[mi][ni], a[mi], bf[ni]);
        }
    }

    // Writeback: bias + relu -> fp16 NHWC (co < 100 only).
#pragma unroll
    for (int mi = 0; mi < 4; mi++) {
        if (mi >= nmi) break;
        int co_a = co0 + mi * 16 + g;
        int co_b = co_a + 8;
        float ba = (co_a < F) ? bias[co_a] : 0.f;
        float bb = (co_b < F) ? bias[co_b] : 0.f;
#pragma unroll
        for (int ni = 0; ni < 4; ni++) {
            int py = tileY + nw * 2 + (ni >> 1);
            int px = tileX + ((ni & 1) << 3) + 2 * tg;
            size_t base = ((size_t)(b * HW + py) * HW + px) * CP;
            if (co_a < F) {
                float v0 = acc[mi][ni][0] + ba; v0 = v0 > 0.f ? v0 : 0.f;
                float v1 = acc[mi][ni][1] + ba; v1 = v1 > 0.f ? v1 : 0.f;
                out[base + co_a] = __float2half(v0);
                out[base + CP + co_a] = __float2half(v1);
            }
            if (co_b < F) {
                float v2 = acc[mi][ni][2] + bb; v2 = v2 > 0.f ? v2 : 0.f;
                float v3 = acc[mi][ni][3] + bb; v3 = v3 > 0.f ? v3 : 0.f;
                out[base + co_b] = __float2half(v2);
                out[base + CP + co_b] = __float2half(v3);
            }
        }
    }
}

// ---------------------------------------------------------------------------
// Hidden conv 5x5 (100->100) + relu, fp16 tensor cores. (Round-12, unchanged.)
// ---------------------------------------------------------------------------
__global__ __launch_bounds__(256, 2)
void conv_hidden(const __half* __restrict__ act_in, const __half* __restrict__ wt,
                 const float* __restrict__ bias, __half* __restrict__ act_out) {
    extern __shared__ __align__(128) __half smem[];
    __half* s_patch = smem;                     // 240 pixel slots * PP halves
    __half* s_A = smem + 240 * PP;              // 2 buffers * 112 * PP
    const uint32_t A_BYTES = 112 * PP * 2;      // 25088

    const int t = threadIdx.x;
    const int lane = t & 31, w = t >> 5;
    const int nw = w & 3, mw = w >> 2;
    const int g = lane >> 2, tg = lane & 3;
    const int tileX = (blockIdx.x % 12) * 16;
    const int tileY = (blockIdx.x / 12) * 8;
    const int b = blockIdx.z;
    const int co0 = mw * 64;
    const int nmi = mw ? 3 : 4;

    const uint32_t sp = smem_u32(s_patch);
    const uint32_t sA0 = smem_u32(s_A);

    {
        const __half* actb = act_in + (size_t)b * HW * HW * CP;
        for (int i = t; i < 240 * 14; i += 256) {
            int pix = i / 14, j = i % 14;
            int r = pix / 20, c = pix % 20;
            int gy = tileY + r - 2, gx = tileX + c - 2;
            bool ok = (unsigned)gy < HW && (unsigned)gx < HW;
            const char* src = ok
                ? (const char*)&actb[((size_t)gy * HW + gx) * CP] + j * 16
                : (const char*)actb;
            uint32_t dst = sp + (uint32_t)pix * (PP * 2) +
                           ((uint32_t)(j * 16) ^ (((pix >> 2) & 1) << 4));
            cp16z(dst, src, ok ? 16 : 0);
        }
    }
    {
        const char* wsrc = (const char*)wt;
        for (int i = t; i < 1568; i += 256)
            cp16(sA0 + (uint32_t)i * 16, wsrc + (size_t)i * 16);
    }
    cp_commit();

    uint32_t a_base[4];
#pragma unroll
    for (int mi = 0; mi < 4; mi++) {
        int row = co0 + mi * 16 + (lane & 15);
        if (row > 111) row = 111;
        uint32_t acol2 = (uint32_t)(lane >> 4) * 16;
        a_base[mi] = sA0 + (uint32_t)row * (PP * 2) +
                     (acol2 ^ (((uint32_t)(row >> 2) & 1) << 4));
    }

    uint32_t b_base[2];
    uint32_t s0pack = 0;
    {
        int sub = lane >> 3, pix = lane & 7;
#pragma unroll
        for (int j = 0; j < 2; j++) {
            int ni = 2 * j + (sub >> 1);
            int khalf = sub & 1;
            int pr0 = nw * 2 + (ni >> 1);
            int pc0 = (ni & 1) * 8 + pix;
            int s0 = pr0 * 20 + pc0;
            b_base[j] = sp + (uint32_t)s0 * (PP * 2) + (uint32_t)khalf * 16;
            s0pack |= (uint32_t)s0 << (8 * j);
        }
    }

    float acc[4][4][4];
#pragma unroll
    for (int mi = 0; mi < 4; mi++)
#pragma unroll
        for (int ni = 0; ni < 4; ni++)
#pragma unroll
            for (int p = 0; p < 4; p++) acc[mi][ni][p] = 0.f;

    cp_wait<0>();
    __syncthreads();

#pragma unroll 1
    for (int tap = 0; tap < 25; tap++) {
        if (tap < 24) {
            const char* wsrc = (const char*)(wt + (size_t)(tap + 1) * 128 * CP);
            uint32_t dst = sA0 + ((tap + 1) & 1) * A_BYTES;
            for (int i = t; i < 1568; i += 256)
                cp16(dst + (uint32_t)i * 16, wsrc + (size_t)i * 16);
            cp_commit();
        }

        const uint32_t aoff = (tap & 1) * A_BYTES;
        const int ky = tap / 5, kx = tap % 5;
        const int ds = ky * 20 + kx;
        const uint32_t dsb = (uint32_t)ds * (PP * 2);

        uint32_t b_tap[2];
#pragma unroll
        for (int j = 0; j < 2; j++) {
            uint32_t s0j = (s0pack >> (8 * j)) & 255u;
            uint32_t swz = ((s0j + (uint32_t)ds) << 2) & 16u;
            b_tap[j] = (b_base[j] + dsb) ^ swz;
        }

        if (mw == 0) {
#pragma unroll
            for (int kc = 0; kc < CP; kc += 16) {
                uint32_t a[4][4];
#pragma unroll
                for (int mi = 0; mi < 4; mi++) ldm_x4(a[mi], a_base[mi] + aoff + kc * 2);
                uint32_t bf[4][2];
#pragma unroll
                for (int j = 0; j < 2; j++) {
                    uint32_t r[4];
                    ldm_x4(r, b_tap[j] + kc * 2);
                    bf[2 * j][0] = r[0]; bf[2 * j][1] = r[1];
                    bf[2 * j + 1][0] = r[2]; bf[2 * j + 1][1] = r[3];
                }
#pragma unroll
                for (int mi = 0; mi < 4; mi++)
#pragma unroll
                    for (int ni = 0; ni < 4; ni++)
                        mma16816(acc[mi][ni], a[mi], bf[ni]);
            }
        } else {
#pragma unroll
            for (int kc = 0; kc < CP; kc += 16) {
                uint32_t a[3][4];
#pragma unroll
                for (int mi = 0; mi < 3; mi++) ldm_x4(a[mi], a_base[mi] + aoff + kc * 2);
                uint32_t bf[4][2];
#pragma unroll
                for (int j = 0; j < 2; j++) {
                    uint32_t r[4];
                    ldm_x4(r, b_tap[j] + kc * 2);
                    bf[2 * j][0] = r[0]; bf[2 * j][1] = r[1];
                    bf[2 * j + 1][0] = r[2]; bf[2 * j + 1][1] = r[3];
                }
#pragma unroll
                for (int mi = 0; mi < 3; mi++)
#pragma unroll
                    for (int ni = 0; ni < 4; ni++)
                        mma16816(acc[mi][ni], a[mi], bf[ni]);
            }
        }

        if (tap < 24) {
            cp_wait<0>();
            __syncthreads();
        }
    }

#pragma unroll
    for (int mi = 0; mi < 4; mi++) {
        if (mi >= nmi) break;
        int co_a = co0 + mi * 16 + g;
        int co_b = co_a + 8;
        float ba = (co_a < F) ? bias[co_a] : 0.f;
        float bb = (co_b < F) ? bias[co_b] : 0.f;
#pragma unroll
        for (int ni = 0; ni < 4; ni++) {
            int py = tileY + nw * 2 + (ni >> 1);
            int px = tileX + ((ni & 1) << 3) + 2 * tg;
            size_t base = ((size_t)(b * HW + py) * HW + px) * CP;
            if (co_a < F) {
                float v0 = acc[mi][ni][0] + ba; v0 = v0 > 0.f ? v0 : 0.f;
                float v1 = acc[mi][ni][1] + ba; v1 = v1 > 0.f ? v1 : 0.f;
                act_out[base + co_a] = __float2half(v0);
                act_out[base + CP + co_a] = __float2half(v1);
            }
            if (co_b < F) {
                float v2 = acc[mi][ni][2] + bb; v2 = v2 > 0.f ? v2 : 0.f;
                float v3 = acc[mi][ni][3] + bb; v3 = v3 > 0.f ? v3 : 0.f;
                act_out[base + co_b] = __float2half(v2);
                act_out[base + CP + co_b] = __float2half(v3);
            }
        }
    }
}

// ---------------------------------------------------------------------------
// Fused kp: GEMM (4 chunks of 128 wkp rows) -> logits in smem transposed,
// then softmax + apply. s_patch aliases dead s_A -> 2 CTAs/SM.
// ---------------------------------------------------------------------------
#define SMEM_KP2 (15360 + 30720 + 59136)

__global__ __launch_bounds__(256, 2)
void kp_fused2(const __half* __restrict__ feat, const float* __restrict__ noisy,
               const __half* __restrict__ wkp, const float* __restrict__ b_kp,
               float* __restrict__ out) {
    extern __shared__ __align__(128) char smc[];
    __half* s_px = (__half*)smc;                            // [64][120]
    __half* s_A = (__half*)(smc + 15360);                   // [128][120]
    __half* s_lg = (__half*)(smc + 15360 + 30720);          // [448][66]
    float* s_patch = (float*)(smc + 15360);                 // aliases s_A

    const int t = threadIdx.x;
    const int lane = t & 31, w = t >> 5;
    const int mw = w & 3, nw = w >> 2;
    const int g = lane >> 2, tg = lane & 3;
    const int tileX = (blockIdx.x % 12) * 16;
    const int tileY = (blockIdx.x / 12) * 4;
    const int b = blockIdx.z;

    {
        const __half* fb = feat + (size_t)b * HW * HW * CP;
        for (int i = t; i < 64 * 14; i += 256) {
            int pix = i / 14, j = i % 14;
            int gy = tileY + (pix >> 4), gx = tileX + (pix & 15);
            ((uint4*)&s_px[pix * PITCH])[j] =
                ((const uint4*)&fb[((size_t)gy * HW + gx) * CP])[j];
        }
    }

    uint32_t a_base[2];
#pragma unroll
    for (int mi = 0; mi < 2; mi++)
        a_base[mi] = smem_u32(&s_A[(mw * 32 + mi * 16 + (lane & 15)) * PITCH +
                                   (lane >> 4) * 8]);
    uint32_t b_base[2];
    {
        int sub = lane >> 3, pix8 = lane & 7;
#pragma unroll
        for (int j = 0; j < 2; j++) {
            int ni = 2 * j + (sub >> 1);
            int khalf = sub & 1;
            int pidx = nw * 32 + ni * 8 + pix8;
            b_base[j] = smem_u32(&s_px[pidx * PITCH + khalf * 8]);
        }
    }

#pragma unroll 1
    for (int cg = 0; cg < 4; cg++) {
        __syncthreads();
        for (int i = t; i < 128 * 14; i += 256) {
            int co = i / 14, j = i % 14;
            int row = cg * 128 + co;
            uint4 v = make_uint4(0, 0, 0, 0);
            if (row < KKP)
                v = ((const uint4*)&wkp[(size_t)row * CP])[j];
            ((uint4*)&s_A[co * PITCH])[j] = v;
        }
        __syncthreads();

        float acc[2][4][4];
#pragma unroll
        for (int mi = 0; mi < 2; mi++)
#pragma unroll
            for (int ni = 0; ni < 4; ni++)
#pragma unroll
                for (int p = 0; p < 4; p++) acc[mi][ni][p] = 0.f;

#pragma unroll
        for (int kc = 0; kc < CP; kc += 16) {
            uint32_t a[2][4];
#pragma unroll
            for (int mi = 0; mi < 2; mi++) ldm_x4(a[mi], a_base[mi] + kc * 2);
            uint32_t bf[4][2];
#pragma unroll
            for (int j = 0; j < 2; j++) {
                uint32_t r[4];
                ldm_x4(r, b_base[j] + kc * 2);
                bf[2 * j][0] = r[0]; bf[2 * j][1] = r[1];
                bf[2 * j + 1][0] = r[2]; bf[2 * j + 1][1] = r[3];
            }
#pragma unroll
            for (int mi = 0; mi < 2; mi++)
#pragma unroll
                for (int ni = 0; ni < 4; ni++)
                    mma16816(acc[mi][ni], a[mi], bf[ni]);
        }

#pragma unroll
        for (int mi = 0; mi < 2; mi++) {
            int co_a = cg * 128 + mw * 32 + mi * 16 + g;
            int co_b = co_a + 8;
            float ba = (co_a < KK) ? b_kp[co_a] : 0.f;
            float bb = (co_b < KK) ? b_kp[co_b] : 0.f;
#pragma unroll
            for (int ni = 0; ni < 4; ni++) {
                int pidx = nw * 32 + ni * 8 + 2 * tg;
                if (co_a < KK) {
                    __half2 h = __floats2half2_rn(acc[mi][ni][0] + ba,
                                                  acc[mi][ni][1] + ba);
                    *(__half2*)&s_lg[co_a * LGP + pidx] = h;
                }
                if (co_b < KK) {
                    __half2 h = __floats2half2_rn(acc[mi][ni][2] + bb,
                                                  acc[mi][ni][3] + bb);
                    *(__half2*)&s_lg[co_b * LGP + pidx] = h;
                }
            }
        }
    }
    __syncthreads();

    for (int i = t; i < 3 * 24 * 36; i += 256) {
        int c = i / (24 * 36);
        int rem = i - c * (24 * 36);
        int dy = rem / 36, dx = rem - dy * 36;
        int gy = tileY + dy - 10, gx = tileX + dx - 10;
        float v = 0.f;
        if ((unsigned)gy < HW && (unsigned)gx < HW)
            v = noisy[(((size_t)b * 3 + c) * HW + gy) * HW + gx];
        s_patch[(c * 24 + dy) * 36 + dx] = v;
    }
    __syncthreads();

#pragma unroll 1
    for (int it = 0; it < 8; it++) {
        int pidx = it * 8 + w;
        int py = pidx >> 4, pxl = pidx & 15;

        float L[14];
#pragma unroll
        for (int i = 0; i < 14; i++) {
            int j = i * 32 + lane;
            L[i] = (j < KK) ? __half2float(s_lg[j * LGP + pidx]) : -1e30f;
        }
        float m = -1e30f;
#pragma unroll
        for (int i = 0; i < 14; i++) m = fmaxf(m, L[i]);
#pragma unroll
        for (int o = 16; o; o >>= 1) m = fmaxf(m, __shfl_xor_sync(0xffffffffu, m, o));

        float se = 0.f, o0 = 0.f, o1 = 0.f, o2 = 0.f;
#pragma unroll
        for (int i = 0; i < 14; i++) {
            int j = i * 32 + lane;
            if (j < KK) {
                float e = __expf(L[i] - m);
                int ky = j / 21, kx = j - ky * 21;
                se += e;
                o0 += e * s_patch[(0 * 24 + py + ky) * 36 + pxl + kx];
                o1 += e * s_patch[(1 * 24 + py + ky) * 36 + pxl + kx];
                o2 += e * s_patch[(2 * 24 + py + ky) * 36 + pxl + kx];
            }
        }
#pragma unroll
        for (int o = 16; o; o >>= 1) {
            se += __shfl_xor_sync(0xffffffffu, se, o);
            o0 += __shfl_xor_sync(0xffffffffu, o0, o);
            o1 += __shfl_xor_sync(0xffffffffu, o1, o);
            o2 += __shfl_xor_sync(0xffffffffu, o2, o);
        }
        if (lane == 0) {
            float inv = 1.f / se;
            int y = tileY + py, x = tileX + pxl;
            out[(((size_t)b * 3 + 0) * HW + y) * HW + x] = o0 * inv;
            out[(((size_t)b * 3 + 1) * HW + y) * HW + x] = o1 * inv;
            out[(((size_t)b * 3 + 2) * HW + y) * HW + x] = o2 * inv;
        }
    }
}

// ---------------------------------------------------------------------------
extern "C" void kernel_launch(void* const* d_in, const int* in_sizes, int n_in,
                              void* d_out, int out_size) {
    const float* noisy = (const float*)d_in[0];
    const float* w_in  = (const float*)d_in[1];
    const float* b_in  = (const float*)d_in[2];
    const float* w_hid = (const float*)d_in[3];
    const float* b_hid = (const float*)d_in[4];
    const float* w_kp  = (const float*)d_in[5];
    const float* b_kp  = (const float*)d_in[6];
    float* out = (float*)d_out;

    __half *act0, *act1, *wt, *wkp, *win;
    cudaGetSymbolAddress((void**)&act0, g_act0);
    cudaGetSymbolAddress((void**)&act1, g_act1);
    cudaGetSymbolAddress((void**)&wt, g_wt);
    cudaGetSymbolAddress((void**)&wkp, g_wkp);
    cudaGetSymbolAddress((void**)&win, g_win);

    const int smem_hidden = 240 * PP * 2 + 2 * 112 * PP * 2;  // 103936 B
    cudaFuncSetAttribute(conv_hidden, cudaFuncAttributeMaxDynamicSharedMemorySize,
                         smem_hidden);
    cudaFuncSetAttribute(kp_fused2, cudaFuncAttributeMaxDynamicSharedMemorySize,
                         SMEM_KP2);
    cudaFuncSetAttribute(conv_in_tc, cudaFuncAttributeMaxDynamicSharedMemorySize,
                         SMEM_CIN);

    wt_transform<<<7 * F, 128>>>(w_hid);
    wkp_transform<<<(KK * F + 255) / 256, 256>>>(w_kp);
    win_transform<<<(5 * CP * PIN + 255) / 256, 256>>>(w_in);

    conv_in_tc<<<dim3(288, 1, 2), 256, SMEM_CIN>>>(noisy, win, b_in, act0);

    const __half* src = act0;
    __half* dst = act1;
    for (int l = 0; l < 7; l++) {
        conv_hidden<<<dim3(288, 1, 2), 256, smem_hidden>>>(
            src, wt + (size_t)l * 25 * 128 * CP, b_hid + l * F, dst);
        __half* tmp = (__half*)src;
        src = dst;
        dst = tmp;
    }

    kp_fused2<<<dim3(576, 1, 2), 256, SMEM_KP2>>>(src, noisy, wkp, b_kp, out);
}